// round 17
// baseline (speedup 1.0000x reference)
#include <cuda_runtime.h>
#include <cuda_fp16.h>
#include <cuda_bf16.h>
#include <math_constants.h>
#include <mma.h>

using namespace nvcuda;

// Problem constants
#define BB    16
#define CC    256
#define HH    32
#define WW    32
#define EE    256
#define NE    8192
#define HW    1024
#define ROWS  16384   // B*H*W
#define KC    2304    // 9*256 im2col K

#define OUT_ELEMS   4194304
#define LOSS_OFF    4194304
#define IDX_OFF     4194305

#define GBLK  512               // gather blocks (ROWS/32)
#define CAND_CAP 256
#define MARGIN 1.2e-3f

// ---------------- device scratch ----------------
__device__ float g_ze[ROWS * EE];      // conv1 out [row][e] (bit-exact)
__device__ float g_zf[ROWS * EE];      // post-LN  [row][e] (bit-exact)
__device__ float g_znorm[ROWS];        // serial sum zf^2
__device__ float g_enorm[NE];          // serial sum e^2
__device__ float g_wp[KC * EE];        // conv1 W permuted [(khw*256+ci)][o]
__device__ int   g_idx[ROWS];
__device__ float g_lpart[GBLK];
__device__ __align__(16) __nv_bfloat16 g_zfh[ROWS * EE];   // zf in bf16
__device__ __align__(16) __nv_bfloat16 g_cbh[NE * EE];     // codebook in bf16
__device__ __align__(16) __half g_w2h[EE * KC];            // conv2 W fp16 [n][kk']
__device__ __align__(16) __half g_zqh[BB * EE * HW];       // zq fp16 x512, NCHW
__device__ int g_cand[(size_t)ROWS * CAND_CAP];            // candidate indices per row
__device__ int g_ccnt[ROWS];                               // candidate counts

// ---------------- helpers ----------------
__device__ __forceinline__ float blk_sum(float v, float* sh) {
    int t = threadIdx.x, lane = t & 31, w = t >> 5;
    #pragma unroll
    for (int o = 16; o; o >>= 1) v += __shfl_down_sync(0xffffffffu, v, o);
    if (!lane) sh[w] = v;
    __syncthreads();
    if (w == 0) {
        float x = (lane < 8) ? sh[lane] : 0.f;
        #pragma unroll
        for (int o = 4; o; o >>= 1) x += __shfl_down_sync(0xffffffffu, x, o);
        if (!lane) sh[0] = x;
    }
    __syncthreads();
    float r = sh[0];
    __syncthreads();
    return r;
}

__device__ __forceinline__ unsigned fenc(float x) {
    unsigned u = __float_as_uint(x);
    return (u & 0x80000000u) ? ~u : (u | 0x80000000u);
}
__device__ __forceinline__ float fdec(unsigned y) {
    unsigned u = (y & 0x80000000u) ? (y ^ 0x80000000u) : ~y;
    return __uint_as_float(u);
}

// ---------------- conv1 weight permute ----------------
__global__ __launch_bounds__(256) void permw_kernel(const float* __restrict__ Wm) {
    int i = blockIdx.x * 256 + threadIdx.x;
    if (i < KC * EE) {
        int o = i & 255;
        int kk = i >> 8;
        int ci = kk & 255;
        int khw = kk >> 8;
        g_wp[kk * 256 + o] = Wm[o * KC + ci * 9 + khw];
    }
}

// ---------------- conv2 weight permute -> fp16 [n][kk'] ----------------
__global__ __launch_bounds__(256) void permw2h_kernel(const float* __restrict__ Wm) {
    int n = blockIdx.x;
    int t = threadIdx.x;
    for (int kk = t; kk < KC; kk += 256) {
        int ci = kk & 255;
        int khw = kk >> 8;
        g_w2h[n * KC + kk] = __float2half(Wm[n * KC + ci * 9 + khw]);
    }
}

// ---------------- enorm3 + codebook->bf16 ----------------
#define LN_STR 260
__global__ __launch_bounds__(256) void enorm3_kernel(const float* __restrict__ cb) {
    __shared__ float ls[32 * LN_STR];
    int t = threadIdx.x;
    int r0 = blockIdx.x * 32;
    const float4* src = (const float4*)(cb + r0 * 256);
    __nv_bfloat162* hc = (__nv_bfloat162*)(g_cbh + r0 * 256);
    #pragma unroll
    for (int e = 0; e < 8; e++) {
        int lin = t + (e << 8);
        float4 v = src[lin];
        hc[2 * lin]     = __floats2bfloat162_rn(v.x, v.y);
        hc[2 * lin + 1] = __floats2bfloat162_rn(v.z, v.w);
        int row = lin >> 6;
        int kq = (lin & 63) << 2;
        *(float4*)&ls[row * LN_STR + kq] = v;
    }
    __syncthreads();
    if (t < 32) {
        const float* x = ls + t * LN_STR;
        float s = 0.f;
        for (int k = 0; k < 256; k++)
            s = __fadd_rn(s, __fmul_rn(x[k], x[k]));
        g_enorm[r0 + t] = s;
    }
}

// ---------------- conv1: bit-exact serial-k im2col GEMM (unchanged) ----------------
__global__ __launch_bounds__(256, 2) void conv1_exact(const float* __restrict__ X,
                                                      const float* __restrict__ bias) {
    __shared__ float As[16][132];
    __shared__ float Bs[16][132];

    int t = threadIdx.x;
    int tx = t & 15, ty = t >> 4;
    int row0 = blockIdx.x * 128;
    int n0 = blockIdx.y * 128;

    float acc[8][8];
    #pragma unroll
    for (int i = 0; i < 8; i++)
        #pragma unroll
        for (int j = 0; j < 8; j++) acc[i][j] = 0.f;

    for (int k0 = 0; k0 < KC; k0 += 16) {
        #pragma unroll
        for (int e = 0; e < 8; e++) {
            int lin = t + e * 256;
            int m = lin & 127, k = lin >> 7;
            int kk = k0 + k;
            int ci = kk & 255;
            int khw = kk >> 8;
            int kh = khw / 3, kw = khw - kh * 3;
            int row = row0 + m;
            int b = row >> 10;
            int hw = row & 1023;
            int h = (hw >> 5) + kh - 1;
            int w = (hw & 31) + kw - 1;
            float v = 0.f;
            if ((unsigned)h < 32u && (unsigned)w < 32u)
                v = X[((b * 256 + ci) << 10) + (h << 5) + w];
            As[k][m] = v;
            Bs[k][m] = g_wp[(k0 + k) * 256 + n0 + m];
        }
        __syncthreads();
        #pragma unroll
        for (int k = 0; k < 16; k++) {
            float a[8], b2[8];
            #pragma unroll
            for (int i = 0; i < 8; i++) a[i] = As[k][ty * 8 + i];
            #pragma unroll
            for (int j = 0; j < 8; j++) b2[j] = Bs[k][tx * 8 + j];
            #pragma unroll
            for (int i = 0; i < 8; i++)
                #pragma unroll
                for (int j = 0; j < 8; j++)
                    acc[i][j] = __fmaf_rn(a[i], b2[j], acc[i][j]);
        }
        __syncthreads();
    }

    #pragma unroll
    for (int i = 0; i < 8; i++) {
        int row = row0 + ty * 8 + i;
        #pragma unroll
        for (int j = 0; j < 8; j++) {
            int n = n0 + tx * 8 + j;
            g_ze[row * 256 + n] = __fadd_rn(acc[i][j], bias[n]);
        }
    }
}

// ---------------- ln3 + zf->bf16 ----------------
__global__ __launch_bounds__(256) void ln3_kernel(const float* __restrict__ g,
                                                  const float* __restrict__ be) {
    __shared__ float ls[32 * LN_STR];
    __shared__ float gg[256], bb[256];
    int t = threadIdx.x;
    int r0 = blockIdx.x * 32;
    gg[t] = g[t];
    bb[t] = be[t];
    const float4* src = (const float4*)(g_ze + r0 * 256);
    #pragma unroll
    for (int e = 0; e < 8; e++) {
        int lin = t + (e << 8);
        float4 v = src[lin];
        int row = lin >> 6;
        int kq = (lin & 63) << 2;
        *(float4*)&ls[row * LN_STR + kq] = v;
    }
    __syncthreads();
    if (t < 32) {
        float* x = ls + t * LN_STR;
        float s = 0.f;
        for (int k = 0; k < 256; k++) s = __fadd_rn(s, x[k]);
        float mu = __fmul_rn(s, 1.f / 256.f);
        float s2 = 0.f;
        for (int k = 0; k < 256; k++) {
            float tq = __fsub_rn(x[k], mu);
            s2 = __fadd_rn(s2, __fmul_rn(tq, tq));
        }
        float var = __fmul_rn(s2, 1.f / 256.f);
        float rs = __fdiv_rn(1.0f, __fsqrt_rn(__fadd_rn(var, 1e-5f)));
        float zn = 0.f;
        for (int k = 0; k < 256; k++) {
            float tq = __fsub_rn(x[k], mu);
            float a = __fmul_rn(tq, rs);
            float v = __fadd_rn(__fmul_rn(a, gg[k]), bb[k]);
            x[k] = v;
            zn = __fadd_rn(zn, __fmul_rn(v, v));
        }
        g_znorm[r0 + t] = zn;
    }
    __syncthreads();
    float4* dst = (float4*)(g_zf + r0 * 256);
    __nv_bfloat162* hz = (__nv_bfloat162*)(g_zfh + r0 * 256);
    #pragma unroll
    for (int e = 0; e < 8; e++) {
        int lin = t + (e << 8);
        int row = lin >> 6;
        int kq = (lin & 63) << 2;
        float4 v = *(const float4*)&ls[row * LN_STR + kq];
        dst[lin] = v;
        hz[2 * lin]     = __floats2bfloat162_rn(v.x, v.y);
        hz[2 * lin + 1] = __floats2bfloat162_rn(v.z, v.w);
    }
}

// ---------------- dist_fused: 32-row blocks sweep all n; running-min candidate collect ----------------
// Approx v via bf16 TC; per-tile: update running per-row min, collect n with
// v <= runningmin + MARGIN (superset of final threshold set) into g_cand.
#define ASTR 264
#define BSPD 72
__global__ __launch_bounds__(256) void dist_fused() {
    __shared__ __nv_bfloat16 As[32 * ASTR];     // 16.9 KB (resident A: 32 rows x 256 k)
    __shared__ __nv_bfloat16 Bs[128 * BSPD];    // 18.4 KB (B chunk: 128 n x 64 k)
    __shared__ float scr[8][320];               // 10.2 KB
    __shared__ float enormS[128];
    __shared__ unsigned sMin[32];
    __shared__ float rowMinS[32];
    __shared__ float thrS[32];
    __shared__ int   cntS[32];

    int t = threadIdx.x;
    int r0g = blockIdx.x * 32;
    int wid = t >> 5, lane = t & 31;
    int wm = (wid & 1) * 16;                    // warp row offset (0/16)
    int wn = (wid >> 1) * 32;                   // warp col offset (0..96)

    // resident A load: 32 rows x 256 k bf16
    #pragma unroll
    for (int e = 0; e < 2; e++) {
        int lin = t + e * 256;                  // 0..511
        int m = lin >> 4;
        int q = (lin & 15) * 16;
        *(uint4*)&As[m * ASTR + q]     = *(const uint4*)&g_zfh[(r0g + m) * 256 + q];
        *(uint4*)&As[m * ASTR + q + 8] = *(const uint4*)&g_zfh[(r0g + m) * 256 + q + 8];
    }
    if (t < 32) { rowMinS[t] = CUDART_INF_F; cntS[t] = 0; sMin[t] = 0xFFFFFFFFu; }
    __syncthreads();

    for (int nt = 0; nt < 64; nt++) {
        int n0 = nt * 128;

        wmma::fragment<wmma::accumulator, 16, 16, 16, float> acc[2];
        #pragma unroll
        for (int f = 0; f < 2; f++) wmma::fill_fragment(acc[f], 0.0f);

        for (int kc = 0; kc < 4; kc++) {
            int k0 = kc * 64;
            // B chunk load: 128 n x 64 k
            #pragma unroll
            for (int e = 0; e < 4; e++) {
                int lin = t + e * 256;          // 0..1023
                int n = lin >> 3;
                int q = (lin & 7) << 3;
                *(uint4*)&Bs[n * BSPD + q] = *(const uint4*)&g_cbh[(n0 + n) * 256 + k0 + q];
            }
            if (kc == 0 && t < 128) enormS[t] = g_enorm[n0 + t];
            __syncthreads();
            #pragma unroll
            for (int ks = 0; ks < 4; ks++) {
                int kk = ks * 16;
                wmma::fragment<wmma::matrix_a, 16, 16, 16, __nv_bfloat16, wmma::row_major> af;
                wmma::fragment<wmma::matrix_b, 16, 16, 16, __nv_bfloat16, wmma::col_major> bf[2];
                wmma::load_matrix_sync(af, &As[wm * ASTR + k0 + kk], ASTR);
                #pragma unroll
                for (int f = 0; f < 2; f++)
                    wmma::load_matrix_sync(bf[f], &Bs[(wn + 16 * f) * BSPD + kk], BSPD);
                #pragma unroll
                for (int f = 0; f < 2; f++)
                    wmma::mma_sync(acc[f], af, bf[f], acc[f]);
            }
            __syncthreads();
        }

        // epilogue: v into regs + per-row tile-min
        float vreg[2][4][2];
        #pragma unroll
        for (int f = 0; f < 2; f++) {
            wmma::store_matrix_sync(scr[wid], acc[f], 20, wmma::mem_row_major);
            __syncwarp();
            #pragma unroll
            for (int e = 0; e < 4; e++) {
                int idx = lane + e * 32;         // 0..127
                int rr = idx >> 3, ccp = idx & 7;
                int lcol = wn + 16 * f + ccp * 2;
                float v0 = enormS[lcol]     - 2.f * scr[wid][rr * 20 + ccp * 2];
                float v1 = enormS[lcol + 1] - 2.f * scr[wid][rr * 20 + ccp * 2 + 1];
                vreg[f][e][0] = v0;
                vreg[f][e][1] = v1;
                float mv = fminf(v0, v1);
                mv = fminf(mv, __shfl_down_sync(0xffffffffu, mv, 4));
                mv = fminf(mv, __shfl_down_sync(0xffffffffu, mv, 2));
                mv = fminf(mv, __shfl_down_sync(0xffffffffu, mv, 1));
                if ((lane & 7) == 0) atomicMin(&sMin[wm + rr], fenc(mv));
            }
            __syncwarp();
        }
        __syncthreads();

        // merge tile min into running min, publish threshold, reset sMin
        if (t < 32) {
            float rm = fminf(rowMinS[t], fdec(sMin[t]));
            rowMinS[t] = rm;
            thrS[t] = rm + MARGIN;
            sMin[t] = 0xFFFFFFFFu;
        }
        __syncthreads();

        // collect candidates from regs (superset-safe: thr only shrinks later)
        #pragma unroll
        for (int f = 0; f < 2; f++)
            #pragma unroll
            for (int e = 0; e < 4; e++) {
                int idx = lane + e * 32;
                int rr = idx >> 3, ccp = idx & 7;
                int lrow = wm + rr;
                float thr = thrS[lrow];
                int ncol = n0 + wn + 16 * f + ccp * 2;
                if (vreg[f][e][0] <= thr) {
                    int p = atomicAdd(&cntS[lrow], 1);
                    if (p < CAND_CAP) g_cand[(size_t)(r0g + lrow) * CAND_CAP + p] = ncol;
                }
                if (vreg[f][e][1] <= thr) {
                    int p = atomicAdd(&cntS[lrow], 1);
                    if (p < CAND_CAP) g_cand[(size_t)(r0g + lrow) * CAND_CAP + p] = ncol + 1;
                }
            }
        // no sync needed: next tile's Bs-load syncthreads orders everything
    }
    __syncthreads();
    if (t < 32) g_ccnt[r0g + t] = min(cntS[t], CAND_CAP);
}

// ---------------- rescore: exact serial-chain d over candidates, lexicographic min ----------------
__global__ __launch_bounds__(256) void rescore_kernel(const float* __restrict__ cb) {
    __shared__ float zfs[4][260];
    __shared__ unsigned long long bestkey[4];
    __shared__ float cscr[8][264];

    int t = threadIdx.x;
    int r0 = blockIdx.x * 4;
    #pragma unroll
    for (int e = 0; e < 4; e++) {
        int lin = t + e * 256;
        zfs[lin >> 8][lin & 255] = g_zf[(r0 + (lin >> 8)) * 256 + (lin & 255)];
    }
    if (t < 4) bestkey[t] = 0xFFFFFFFFFFFFFFFFull;
    __syncthreads();

    int wid = t >> 5, lane = t & 31;
    for (int r = 0; r < 4; r++) {
        int row = r0 + r;
        int H = g_ccnt[row];
        for (int h = wid; h < H; h += 8) {
            int n = g_cand[(size_t)row * CAND_CAP + h];
            #pragma unroll
            for (int e = 0; e < 8; e++)
                cscr[wid][lane + e * 32] = cb[n * 256 + lane + e * 32];
            __syncwarp();
            if (lane == 0) {
                float dot = 0.f;
                for (int k = 0; k < 256; k++)
                    dot = __fmaf_rn(zfs[r][k], cscr[wid][k], dot);
                float S = __fadd_rn(g_znorm[row], g_enorm[n]);
                float d = __fsub_rn(S, __fmul_rn(2.0f, dot));
                unsigned long long key =
                    (((unsigned long long)__float_as_uint(d)) << 32) | (unsigned)n;
                atomicMin(&bestkey[r], key);
            }
            __syncwarp();
        }
    }
    __syncthreads();
    if (t < 4) g_idx[r0 + t] = (int)(bestkey[t] & 0xFFFFFFFFull);
}

// ---------------- gather2: straight-through -> fp16 x512 NCHW + loss partials ----------------
#define SC512 512.0f
#define INV512 (1.0f / 512.0f)
__global__ __launch_bounds__(256) void gather2_kernel(const float* __restrict__ cb) {
    __shared__ float sq[256][33];
    __shared__ int sid[32];
    __shared__ float sh[32];
    int t = threadIdx.x;
    int r0 = blockIdx.x * 32;
    if (t < 32) sid[t] = g_idx[r0 + t];
    __syncthreads();
    float local = 0.f;
    #pragma unroll 4
    for (int i = 0; i < 32; i++) {
        float e = cb[sid[i] * 256 + t];
        float z = g_ze[(r0 + i) * 256 + t];
        float d = __fsub_rn(e, z);
        sq[t][i] = __fadd_rn(z, d);
        local += d * d;
    }
    __syncthreads();
    int b = r0 >> 10, hw0 = r0 & 1023;
    int w = t >> 5, lane = t & 31;
    #pragma unroll 4
    for (int eb = 0; eb < 32; eb++) {
        int e = eb * 8 + w;
        g_zqh[((b * 256 + e) << 10) + hw0 + lane] = __float2half(sq[e][lane] * SC512);
    }
    float s = blk_sum(local, sh);
    if (t == 0) g_lpart[blockIdx.x] = s;
}

// ---------------- conv2_wmma: fp16 TC conv2 (A pre-scaled x512, k-order khw-major) ----------------
#define BSP 72
__global__ __launch_bounds__(256) void conv2_wmma(const float* __restrict__ bias,
                                                  float* __restrict__ outNCHW) {
    __shared__ __half As2[128 * BSP];
    __shared__ __half Bs2[128 * BSP];
    __shared__ float scr[8][320];
    int t = threadIdx.x;
    int row0 = blockIdx.x * 128;
    int n0 = blockIdx.y * 128;
    int wid = t >> 5, lane = t & 31;
    int wm = (wid & 3) * 32;
    int wn = (wid >> 2) * 64;

    wmma::fragment<wmma::accumulator, 16, 16, 16, float> acc[2][4];
    #pragma unroll
    for (int i = 0; i < 2; i++)
        #pragma unroll
        for (int j = 0; j < 4; j++) wmma::fill_fragment(acc[i][j], 0.0f);

    const __half hzero = __float2half(0.f);
    for (int k0 = 0; k0 < KC; k0 += 64) {
        #pragma unroll
        for (int e = 0; e < 32; e++) {
            int lin = t + e * 256;
            int m = lin & 127, k = lin >> 7;
            int kk = k0 + k;
            int ci = kk & 255;
            int khw = kk >> 8;
            int kh = khw / 3, kw = khw - kh * 3;
            int row = row0 + m;
            int b = row >> 10;
            int hw = row & 1023;
            int h = (hw >> 5) + kh - 1;
            int w = (hw & 31) + kw - 1;
            __half v = hzero;
            if ((unsigned)h < 32u && (unsigned)w < 32u)
                v = g_zqh[((b * 256 + ci) << 10) + (h << 5) + w];
            As2[m * BSP + k] = v;
        }
        #pragma unroll
        for (int e = 0; e < 4; e++) {
            int lin = t + e * 256;
            int n = lin >> 3;
            int q = (lin & 7) << 3;
            *(uint4*)&Bs2[n * BSP + q] = *(const uint4*)&g_w2h[(n0 + n) * KC + k0 + q];
        }
        __syncthreads();
        #pragma unroll
        for (int ks = 0; ks < 4; ks++) {
            int kk = ks * 16;
            wmma::fragment<wmma::matrix_a, 16, 16, 16, __half, wmma::row_major> af[2];
            wmma::fragment<wmma::matrix_b, 16, 16, 16, __half, wmma::col_major> bf[4];
            #pragma unroll
            for (int i = 0; i < 2; i++)
                wmma::load_matrix_sync(af[i], &As2[(wm + 16 * i) * BSP + kk], BSP);
            #pragma unroll
            for (int j = 0; j < 4; j++)
                wmma::load_matrix_sync(bf[j], &Bs2[(wn + 16 * j) * BSP + kk], BSP);
            #pragma unroll
            for (int i = 0; i < 2; i++)
                #pragma unroll
                for (int j = 0; j < 4; j++)
                    wmma::mma_sync(acc[i][j], af[i], bf[j], acc[i][j]);
        }
        __syncthreads();
    }

    #pragma unroll
    for (int i = 0; i < 2; i++)
        #pragma unroll
        for (int j = 0; j < 4; j++) {
            wmma::store_matrix_sync(scr[wid], acc[i][j], 20, wmma::mem_row_major);
            __syncwarp();
            #pragma unroll
            for (int e = 0; e < 8; e++) {
                int idx = lane + e * 32;
                int rr = idx & 15, cc = idx >> 4;
                int row = row0 + wm + 16 * i + rr;
                int n = n0 + wn + 16 * j + cc;
                int b = row >> 10;
                int hw = row & 1023;
                outNCHW[((b * 256 + n) << 10) + hw] =
                    __fmaf_rn(scr[wid][rr * 20 + cc], INV512, bias[n]);
            }
            __syncwarp();
        }
}

// ---------------- finalize ----------------
__global__ __launch_bounds__(256) void finalize_kernel(float* __restrict__ out, int out_size) {
    __shared__ float sh[32];
    int gidx = blockIdx.x * blockDim.x + threadIdx.x;
    if (gidx < ROWS && IDX_OFF + gidx < out_size)
        out[IDX_OFF + gidx] = (float)g_idx[gidx];
    if (blockIdx.x == 0) {
        float s = 0.f;
        for (int k = threadIdx.x; k < GBLK; k += 256) s += g_lpart[k];
        float tot = blk_sum(s, sh);
        if (threadIdx.x == 0 && LOSS_OFF < out_size)
            out[LOSS_OFF] = 1.25f * tot / (float)OUT_ELEMS;
    }
}

// ---------------- launcher ----------------
extern "C" void kernel_launch(void* const* d_in, const int* in_sizes, int n_in,
                              void* d_out, int out_size) {
    (void)in_sizes; (void)n_in;
    const float* z       = (const float*)d_in[0];
    const float* emb_w   = (const float*)d_in[1];
    const float* emb_b   = (const float*)d_in[2];
    const float* ln_g    = (const float*)d_in[3];
    const float* ln_b    = (const float*)d_in[4];
    const float* cb      = (const float*)d_in[5];
    const float* unemb_w = (const float*)d_in[6];
    const float* unemb_b = (const float*)d_in[7];
    float* out = (float*)d_out;

    permw_kernel<<<(KC * EE + 255) / 256, 256>>>(emb_w);
    permw2h_kernel<<<EE, 256>>>(unemb_w);
    enorm3_kernel<<<NE / 32, 256>>>(cb);                                  // enorm + cbh
    conv1_exact<<<dim3(ROWS / 128, 2), 256>>>(z, emb_b);                  // -> g_ze
    ln3_kernel<<<ROWS / 32, 256>>>(ln_g, ln_b);                           // -> g_zf/zfh/znorm
    dist_fused<<<ROWS / 32, 256>>>();                                     // -> g_cand/g_ccnt
    rescore_kernel<<<ROWS / 4, 256>>>(cb);                                // -> g_idx (exact)
    gather2_kernel<<<GBLK, 256>>>(cb);                                    // -> g_zqh, g_lpart
    conv2_wmma<<<dim3(ROWS / 128, 2), 256>>>(unemb_b, out);               // -> out (fp16 TC)
    finalize_kernel<<<ROWS / 256, 256>>>(out, out_size);
}